// round 13
// baseline (speedup 1.0000x reference)
#include <cuda_runtime.h>
#include <cuda_bf16.h>
#include <cuda_fp16.h>
#include <cstdint>
#include <math.h>

#define NN 100000
#define NE 600000
#define DD 128
#define CAP 64
#define NTILES 782                 // ceil(100000/128)
#define TILES_TOTAL (3 * NTILES)
#define OVF_MAX 4096

typedef unsigned long long u64;
typedef unsigned int u32;

// ---------------- device scratch ------------------------------------------------------
__device__ float g_agg[3 * NN * DD];          // f32 aggregates: [geo, trans, cat]
__device__ __nv_bfloat16 g_aggh[3 * NN * DD]; // bf16 copy for att staging
__device__ u32 g_deg[3 * NN];
__device__ int g_bucket[3 * NN * CAP];
__device__ float g_bw[NN * CAP];              // weights for trans buckets
__device__ float g_wcomb[512 * DD];           // W1 @ W_tran
__device__ float g_wsum[3];
__device__ u32 g_ovf_cnt;
__device__ int g_ovf[OVF_MAX * 4];            // rel, dst, src, w-bits

// ---------------- small PTX helpers ---------------------------------------------------
__device__ __forceinline__ u64 pack2(float x) {
    u64 r; asm("mov.b64 %0, {%1, %1};" : "=l"(r) : "f"(x)); return r;
}
__device__ __forceinline__ void ffma2(u64& d, u64 a, u64 b) {
    asm("fma.rn.f32x2 %0, %1, %2, %0;" : "+l"(d) : "l"(a), "l"(b));
}
__device__ __forceinline__ float2 unpack2(u64 v) {
    float2 f; asm("mov.b64 {%0, %1}, %2;" : "=f"(f.x), "=f"(f.y) : "l"(v)); return f;
}
__device__ __forceinline__ __half2 tanh2(__half2 x) {
    u32 xi = *(u32*)&x, yi;
    asm("tanh.approx.f16x2 %0, %1;" : "=r"(yi) : "r"(xi));
    return *(__half2*)&yi;
}
__device__ __forceinline__ u32 smem_u32(const void* p) {
    u32 a; asm("{ .reg .u64 t; cvta.to.shared.u64 t, %1; cvt.u32.u64 %0, t; }" : "=r"(a) : "l"(p));
    return a;
}
__device__ __forceinline__ void ldsm_x4(u32& r0, u32& r1, u32& r2, u32& r3, u32 addr) {
    asm volatile("ldmatrix.sync.aligned.m8n8.x4.shared.b16 {%0,%1,%2,%3}, [%4];"
                 : "=r"(r0), "=r"(r1), "=r"(r2), "=r"(r3) : "r"(addr));
}
__device__ __forceinline__ void mma_16816(float* c, u32 a0, u32 a1, u32 a2, u32 a3,
                                          u32 b0, u32 b1) {
    asm volatile(
        "mma.sync.aligned.m16n8k16.row.col.f32.bf16.bf16.f32 "
        "{%0,%1,%2,%3}, {%4,%5,%6,%7}, {%8,%9}, {%0,%1,%2,%3};"
        : "+f"(c[0]), "+f"(c[1]), "+f"(c[2]), "+f"(c[3])
        : "r"(a0), "r"(a1), "r"(a2), "r"(a3), "r"(b0), "r"(b1));
}
__device__ __forceinline__ u64 pack_bf16x4(float x, float y, float z, float w) {
    __nv_bfloat162 p0 = __floats2bfloat162_rn(x, y);
    __nv_bfloat162 p1 = __floats2bfloat162_rn(z, w);
    return (u64)(*(u32*)&p0) | ((u64)(*(u32*)&p1) << 32);
}

// ---------------- stage [128x128] f32 weights into paired-f32x2 smem layout -----------
__device__ __forceinline__ void stage_w128(float* Ws, const float* __restrict__ Wsrc,
                                           int tid, int nthreads) {
    for (int idx = tid; idx < DD * DD; idx += nthreads) {
        int j = idx >> 7, k = idx & 127;
        int l, c;
        if (j < 64) { l = j >> 1; c = j & 1; }
        else        { l = (j - 64) >> 1; c = 2 + ((j - 64) & 1); }
        Ws[(k * 32 + l) * 4 + c] = Wsrc[idx];
    }
}

// ---------------- kernel: prep = zero counters + Wcomb = W1 @ W_tran -------------------
__global__ __launch_bounds__(256) void prep_kernel(const float* __restrict__ W1,
                                                   const float* __restrict__ Wt) {
    int i = blockIdx.x * 256 + threadIdx.x;
    if (i < 512 * DD) {
        int h = i >> 7, j = i & 127;
        float acc = 0.f;
#pragma unroll 8
        for (int k = 0; k < DD; k++)
            acc += W1[h * DD + k] * Wt[k * DD + j];
        g_wcomb[i] = acc;
    }
    int stride = gridDim.x * 256;
    for (int k = i; k < 3 * NN; k += stride) g_deg[k] = 0u;
    if (i < 3) g_wsum[i] = 0.f;
    if (i == 3) g_ovf_cnt = 0u;
}

// ---------------- kernel: fill destination buckets (4 edges, batched atomics) ----------
__global__ __launch_bounds__(256) void fill_kernel(
    const int* __restrict__ gs, const int* __restrict__ gd,
    const int* __restrict__ cs, const int* __restrict__ cd,
    const int* __restrict__ ts, const int* __restrict__ td,
    const float* __restrict__ tw) {
    int i = blockIdx.x * blockDim.x + threadIdx.x;   // i < 3*NE/4 = 450000
    if (i >= 3 * NE / 4) return;
    int rel = i / (NE / 4);
    int e4 = i - rel * (NE / 4);

    int4 sv, dv; float4 wv = make_float4(1.f, 1.f, 1.f, 1.f);
    if (rel == 0)      { sv = ((const int4*)gs)[e4]; dv = ((const int4*)gd)[e4]; }
    else if (rel == 1) { sv = ((const int4*)cs)[e4]; dv = ((const int4*)cd)[e4]; }
    else               { sv = ((const int4*)ts)[e4]; dv = ((const int4*)td)[e4];
                         wv = ((const float4*)tw)[e4]; }

    int src[4] = {sv.x, sv.y, sv.z, sv.w};
    int dst[4] = {dv.x, dv.y, dv.z, dv.w};
    float w[4] = {wv.x, wv.y, wv.z, wv.w};

    // Issue all 4 atomics first (independent L2 round trips), then the dependent stores
    u32 pos[4];
#pragma unroll
    for (int j = 0; j < 4; j++)
        pos[j] = atomicAdd(&g_deg[rel * NN + dst[j]], 1u);

#pragma unroll
    for (int j = 0; j < 4; j++) {
        if (pos[j] < CAP) {
            g_bucket[(rel * NN + dst[j]) * CAP + pos[j]] = src[j];
            if (rel == 2) g_bw[dst[j] * CAP + pos[j]] = w[j];
        } else {
            u32 o = atomicAdd(&g_ovf_cnt, 1u);
            if (o < OVF_MAX) {
                g_ovf[o * 4 + 0] = rel;
                g_ovf[o * 4 + 1] = dst[j];
                g_ovf[o * 4 + 2] = src[j];
                g_ovf[o * 4 + 3] = __float_as_int(w[j]);
            }
        }
    }
}

// ---------------- kernel: per-destination gather-sum (+inline overflow handling) -------
__global__ __launch_bounds__(256) void gather_kernel(const float* __restrict__ feat) {
    int warps_total = gridDim.x * (blockDim.x >> 5);
    int gw0 = blockIdx.x * (blockDim.x >> 5) + (threadIdx.x >> 5);
    int lane = threadIdx.x & 31;
    const float4* f4 = (const float4*)feat;

    for (int gw = gw0; gw < 3 * NN; gw += warps_total) {
        int rel = gw / NN, dst = gw - rel * NN;

        u32 d = g_deg[rel * NN + dst];
        u32 lim = d < CAP ? d : CAP;
        const int4* bkv = (const int4*)&g_bucket[(size_t)(rel * NN + dst) * CAP];

        float4 acc = make_float4(0.f, 0.f, 0.f, 0.f);

        if (rel != 2) {
            for (u32 e = 0; e < lim; e += 8) {
                int4 ia = bkv[e >> 2];
                int4 ib = bkv[(e >> 2) + 1];
                int si[8] = {ia.x, ia.y, ia.z, ia.w, ib.x, ib.y, ib.z, ib.w};
                float4 v[8];
#pragma unroll
                for (int j = 0; j < 8; j++)
                    v[j] = (e + j < lim) ? f4[(u32)si[j] * 32u + lane]
                                         : make_float4(0.f, 0.f, 0.f, 0.f);
#pragma unroll
                for (int j = 0; j < 8; j++) {
                    acc.x += v[j].x; acc.y += v[j].y; acc.z += v[j].z; acc.w += v[j].w;
                }
            }
        } else {
            const float4* bwv = (const float4*)&g_bw[(size_t)dst * CAP];
            for (u32 e = 0; e < lim; e += 8) {
                int4 ia = bkv[e >> 2];
                int4 ib = bkv[(e >> 2) + 1];
                float4 wa = bwv[e >> 2];
                float4 wb = bwv[(e >> 2) + 1];
                int si[8] = {ia.x, ia.y, ia.z, ia.w, ib.x, ib.y, ib.z, ib.w};
                float wi[8] = {wa.x, wa.y, wa.z, wa.w, wb.x, wb.y, wb.z, wb.w};
                float4 v[8];
#pragma unroll
                for (int j = 0; j < 8; j++) {
                    bool p = e + j < lim;
                    v[j] = p ? f4[(u32)si[j] * 32u + lane]
                             : make_float4(0.f, 0.f, 0.f, 0.f);
                    if (!p) wi[j] = 0.f;
                }
#pragma unroll
                for (int j = 0; j < 8; j++) {
                    acc.x += v[j].x * wi[j];
                    acc.y += v[j].y * wi[j];
                    acc.z += v[j].z * wi[j];
                    acc.w += v[j].w * wi[j];
                }
            }
        }

        // Inline overflow handling (statistically never taken: P(deg>64) ~ 1e-44)
        if (d > CAP) {
            u32 cnt = g_ovf_cnt;
            if (cnt > OVF_MAX) cnt = OVF_MAX;
            for (u32 o = 0; o < cnt; o++) {
                if (g_ovf[o * 4 + 0] == rel && g_ovf[o * 4 + 1] == dst) {
                    int src = g_ovf[o * 4 + 2];
                    float w = __int_as_float(g_ovf[o * 4 + 3]);
                    float4 v = f4[(u32)src * 32u + lane];
                    acc.x += v.x * w; acc.y += v.y * w;
                    acc.z += v.z * w; acc.w += v.w * w;
                }
            }
        }

        float sc = (rel == 2) ? 1.f : 1.f / fmaxf((float)d, 1.f);
        acc.x *= sc; acc.y *= sc; acc.z *= sc; acc.w *= sc;

        size_t row = (size_t)(rel * NN + dst);
        ((float4*)g_agg)[row * 32 + lane] = acc;
        ((u64*)g_aggh)[row * 32 + lane] = pack_bf16x4(acc.x, acc.y, acc.z, acc.w);
    }
}

// ---------------- kernel: attention HMMA, 512 threads, R10 tile (32x32/warp) ----------
#define ATT_LDA 136
#define A_BYTES 34816
#define SM_A0  0
#define SM_B   69632
#define SM_B1  208896
#define SM_W2  210944
#define SMEM_ATT 212992
#define ATT_THREADS 512

__global__ __launch_bounds__(ATT_THREADS) void att_mma_kernel(const float* __restrict__ B1,
                                                              const float* __restrict__ W2) {
    extern __shared__ char smem[];
    u32 sb = smem_u32(smem);
    int tid = threadIdx.x, wid = tid >> 5, lane = tid & 31;

    // Stage B = Wcomb (f32 -> bf16), b1, w2
    for (int i = tid; i < 512 * 32; i += ATT_THREADS) {
        int j = i >> 5, q = i & 31;
        float4 v = ((const float4*)g_wcomb)[i];
        *(u64*)(smem + SM_B + (j * ATT_LDA + q * 4) * 2) = pack_bf16x4(v.x, v.y, v.z, v.w);
    }
    if (tid < 512) {
        ((float*)(smem + SM_B1))[tid] = B1[tid];
        ((float*)(smem + SM_W2))[tid] = W2[tid];
    }

    // async A-tile stager: 128 rows x 256B via 16B cp.async chunks (2048 chunks)
    auto stage = [&](int t, int bf) {
        if (t < TILES_TOTAL) {
            int rel = t / NTILES;
            int base = (t - rel * NTILES) * 128;
            const char* srcb = (const char*)g_aggh + (size_t)rel * NN * 256;
#pragma unroll
            for (int k2 = 0; k2 < 4; k2++) {
                int i = tid + k2 * ATT_THREADS;
                int row = i >> 4, q = i & 15;
                int node = base + row;
                bool vld = node < NN;
                const char* src = srcb + (size_t)(vld ? node : 0) * 256 + q * 16;
                u32 dsta = sb + SM_A0 + bf * A_BYTES + row * 272 + q * 16;
                int ss = vld ? 16 : 0;
                asm volatile("cp.async.cg.shared.global [%0], [%1], 16, %2;"
                             :: "r"(dsta), "l"(src), "r"(ss) : "memory");
            }
        }
        asm volatile("cp.async.commit_group;" ::: "memory");
    };

    stage(blockIdx.x, 0);
    __syncthreads();

    const float* b1s = (const float*)(smem + SM_B1);
    const float* w2s = (const float*)(smem + SM_W2);

    // Tile-invariant half2 bias/weight pairs; this warp's 32 cols = 4 n-groups of 8
    __half2 bh[4], wh[4];
#pragma unroll
    for (int nn = 0; nn < 4; nn++) {
        int j0 = (wid << 5) + nn * 8 + ((lane & 3) << 1);
        bh[nn] = __floats2half2_rn(b1s[j0], b1s[j0 + 1]);
        wh[nn] = __floats2half2_rn(w2s[j0], w2s[j0 + 1]);
    }

    float racc[3] = {0.f, 0.f, 0.f};
    int buf = 0;
    u32 grp = lane >> 3, l3 = lane & 7;

    for (int t = blockIdx.x; t < TILES_TOTAL; t += gridDim.x) {
        asm volatile("cp.async.wait_group 0;" ::: "memory");
        __syncthreads();
        stage(t + gridDim.x, buf ^ 1);   // overlap next tile load with compute

        int rel = t / NTILES;
        int base = (t - rel * NTILES) * 128;
        u32 abase = sb + SM_A0 + buf * A_BYTES;
        bool full = (base + 128 <= NN);

        float ps = 0.f;
#pragma unroll
        for (int mp = 0; mp < 4; mp++) {
            int m0 = mp * 32;
            float acc[2][4][4];
#pragma unroll
            for (int s = 0; s < 2; s++)
#pragma unroll
                for (int n = 0; n < 4; n++)
#pragma unroll
                    for (int ee = 0; ee < 4; ee++) acc[s][n][ee] = 0.f;

#pragma unroll
            for (int kk = 0; kk < 8; kk++) {
                u32 a0[4], a1[4];
                u32 arow0 = m0 + (lane & 15);
                u32 acol = kk * 16 + ((lane >> 4) << 3);
                ldsm_x4(a0[0], a0[1], a0[2], a0[3], abase + (arow0 * ATT_LDA + acol) * 2);
                ldsm_x4(a1[0], a1[1], a1[2], a1[3],
                        abase + ((arow0 + 16) * ATT_LDA + acol) * 2);

#pragma unroll
                for (int np = 0; np < 2; np++) {
                    u32 b0, b1r, b2, b3;
                    u32 brow = (wid << 5) + np * 16 + ((grp >> 1) << 3) + l3;
                    u32 bcol = kk * 16 + ((grp & 1) << 3);
                    ldsm_x4(b0, b1r, b2, b3, sb + SM_B + (brow * ATT_LDA + bcol) * 2);
                    mma_16816(acc[0][np * 2], a0[0], a0[1], a0[2], a0[3], b0, b1r);
                    mma_16816(acc[1][np * 2], a1[0], a1[1], a1[2], a1[3], b0, b1r);
                    mma_16816(acc[0][np * 2 + 1], a0[0], a0[1], a0[2], a0[3], b2, b3);
                    mma_16816(acc[1][np * 2 + 1], a1[0], a1[1], a1[2], a1[3], b2, b3);
                }
            }

            // Epilogue (f16x2): hsum += wh * tanh(acc + bh)
            __half2 hsum = __floats2half2_rn(0.f, 0.f);
            if (full) {
#pragma unroll
                for (int nn = 0; nn < 4; nn++) {
#pragma unroll
                    for (int s = 0; s < 2; s++) {
                        const float* c = acc[s][nn];
                        __half2 x0 = __hadd2(__floats2half2_rn(c[0], c[1]), bh[nn]);
                        hsum = __hfma2(tanh2(x0), wh[nn], hsum);
                        __half2 x1 = __hadd2(__floats2half2_rn(c[2], c[3]), bh[nn]);
                        hsum = __hfma2(tanh2(x1), wh[nn], hsum);
                    }
                }
            } else {
                bool v0 = (base + m0 + (lane >> 2)) < NN;
                bool v1 = (base + m0 + 8 + (lane >> 2)) < NN;
                bool v2 = (base + m0 + 16 + (lane >> 2)) < NN;
                bool v3 = (base + m0 + 24 + (lane >> 2)) < NN;
#pragma unroll
                for (int nn = 0; nn < 4; nn++) {
#pragma unroll
                    for (int s = 0; s < 2; s++) {
                        const float* c = acc[s][nn];
                        bool pa = s ? v2 : v0;
                        bool pb = s ? v3 : v1;
                        if (pa) {
                            __half2 x = __hadd2(__floats2half2_rn(c[0], c[1]), bh[nn]);
                            hsum = __hfma2(tanh2(x), wh[nn], hsum);
                        }
                        if (pb) {
                            __half2 x = __hadd2(__floats2half2_rn(c[2], c[3]), bh[nn]);
                            hsum = __hfma2(tanh2(x), wh[nn], hsum);
                        }
                    }
                }
            }
            float2 hs = __half22float2(hsum);
            ps += hs.x + hs.y;
        }
        racc[rel] += ps;
        buf ^= 1;
    }

#pragma unroll
    for (int o = 16; o; o >>= 1) {
        racc[0] += __shfl_xor_sync(0xffffffffu, racc[0], o);
        racc[1] += __shfl_xor_sync(0xffffffffu, racc[1], o);
        racc[2] += __shfl_xor_sync(0xffffffffu, racc[2], o);
    }
    if (lane == 0) {
        atomicAdd(&g_wsum[0], racc[0]);
        atomicAdd(&g_wsum[1], racc[1]);
        atomicAdd(&g_wsum[2], racc[2]);
    }
}

// ---------------- kernel: fuse, 8 nodes/warp/iter (LDS-balanced f32x2 microkernel) -----
// smem: Ws 65536 (paired W layout) + Zs 65536 (8 warps * 8 nodes * 128 * 8B) = 131072.
__global__ __launch_bounds__(256) void fuse_kernel(const float* __restrict__ Wt,
                                                   float* __restrict__ out) {
    extern __shared__ char smem[];
    float* Ws = (float*)smem;                  // 65536 B
    u64* Zs = (u64*)(smem + 65536);            // 65536 B
    int tid = threadIdx.x;
    stage_w128(Ws, Wt, tid, 256);
    __syncthreads();

    float w0 = g_wsum[0] * (1.f / NN);
    float w1 = g_wsum[1] * (1.f / NN);
    float w2 = g_wsum[2] * (1.f / NN);
    float m = fmaxf(w0, fmaxf(w1, w2));
    float e0 = expf(w0 - m), e1 = expf(w1 - m), e2 = expf(w2 - m);
    float inv = 1.f / (e0 + e1 + e2);
    float b0 = e0 * inv, b1 = e1 * inv, b2 = e2 * inv;

    const ulonglong2* Wv = (const ulonglong2*)Ws;
    int warp = tid >> 5, lane = tid & 31;
    u64* Zw = Zs + warp * 8 * DD;
    const float4* geo4 = (const float4*)g_agg;
    const float4* trn4 = geo4 + (size_t)NN * 32;
    const float4* cat4 = trn4 + (size_t)NN * 32;

    for (int base = blockIdx.x * 64 + warp * 8; base < NN; base += gridDim.x * 64) {
#pragma unroll
        for (int mm = 0; mm < 8; mm++) {
            int n = base + mm;
            float4 v = make_float4(0.f, 0.f, 0.f, 0.f);
            if (n < NN) {
                float4 g = geo4[(size_t)n * 32 + lane];
                float4 t = trn4[(size_t)n * 32 + lane];
                float4 c = cat4[(size_t)n * 32 + lane];
                v.x = b0 * g.x + b1 * t.x + b2 * c.x;
                v.y = b0 * g.y + b1 * t.y + b2 * c.y;
                v.z = b0 * g.z + b1 * t.z + b2 * c.z;
                v.w = b0 * g.w + b1 * t.w + b2 * c.w;
            }
            u64* zp = Zw + mm * DD + lane * 4;
            zp[0] = pack2(v.x); zp[1] = pack2(v.y); zp[2] = pack2(v.z); zp[3] = pack2(v.w);
        }
        __syncwarp();

        u64 acc[8][2];
#pragma unroll
        for (int mm = 0; mm < 8; mm++) { acc[mm][0] = 0ull; acc[mm][1] = 0ull; }

#pragma unroll 2
        for (int k = 0; k < DD; k++) {
            ulonglong2 wv = Wv[k * 32 + lane];
#pragma unroll
            for (int mm = 0; mm < 8; mm++) {
                u64 zz = Zw[mm * DD + k];
                ffma2(acc[mm][0], zz, wv.x);
                ffma2(acc[mm][1], zz, wv.y);
            }
        }

#pragma unroll
        for (int mm = 0; mm < 8; mm++) {
            int n = base + mm;
            if (n < NN) {
                float2 p0 = unpack2(acc[mm][0]);
                float2 p1 = unpack2(acc[mm][1]);
                p0.x = (p0.x >= 0.f) ? p0.x : 0.2f * p0.x;
                p0.y = (p0.y >= 0.f) ? p0.y : 0.2f * p0.y;
                p1.x = (p1.x >= 0.f) ? p1.x : 0.2f * p1.x;
                p1.y = (p1.y >= 0.f) ? p1.y : 0.2f * p1.y;
                ((float2*)out)[n * 64 + lane] = p0;
                ((float2*)out)[n * 64 + 32 + lane] = p1;
            }
        }
        __syncwarp();
    }
}

// ---------------- launcher -------------------------------------------------------------
extern "C" void kernel_launch(void* const* d_in, const int* in_sizes, int n_in,
                              void* d_out, int out_size) {
    const float* feat = (const float*)d_in[0];
    const float* Wt   = (const float*)d_in[1];
    const float* w1   = (const float*)d_in[2];
    const float* b1   = (const float*)d_in[3];
    const float* w2   = (const float*)d_in[4];
    const float* tw   = (const float*)d_in[5];
    const int* gs = (const int*)d_in[6];
    const int* gd = (const int*)d_in[7];
    const int* cs = (const int*)d_in[8];
    const int* cd = (const int*)d_in[9];
    const int* ts = (const int*)d_in[10];
    const int* td = (const int*)d_in[11];
    float* out = (float*)d_out;

    const int SMEM_FUSE = 65536 + 65536;
    cudaFuncSetAttribute(att_mma_kernel, cudaFuncAttributeMaxDynamicSharedMemorySize, SMEM_ATT);
    cudaFuncSetAttribute(fuse_kernel, cudaFuncAttributeMaxDynamicSharedMemorySize, SMEM_FUSE);

    prep_kernel<<<512, 256>>>(w1, Wt);
    fill_kernel<<<(3 * NE / 4 + 255) / 256, 256>>>(gs, gd, cs, cd, ts, td, tw);
    gather_kernel<<<2048, 256>>>(feat);
    att_mma_kernel<<<148, ATT_THREADS, SMEM_ATT>>>(b1, w2);
    fuse_kernel<<<296, 256, SMEM_FUSE>>>(Wt, out);
}

// round 15
// speedup vs baseline: 1.1539x; 1.1539x over previous
#include <cuda_runtime.h>
#include <cuda_fp16.h>
#include <cstdint>
#include <math.h>

#define NN 100000
#define NE 600000
#define DD 128
#define CAP 64
#define NTILES 782                 // ceil(100000/128)
#define TILES_TOTAL (3 * NTILES)
#define OVF_MAX 4096

typedef unsigned long long u64;
typedef unsigned int u32;

// ---------------- device scratch ------------------------------------------------------
__device__ __half g_aggh[3 * NN * DD];        // f16 aggregates: [geo, trans, cat]
__device__ u32 g_deg[3 * NN];
__device__ int g_bucket[3 * NN * CAP];
__device__ float g_bw[NN * CAP];              // weights for trans buckets
__device__ float g_wcomb[512 * DD];           // W1 @ W_tran
__device__ float g_wsum[3];
__device__ u32 g_ovf_cnt;
__device__ int g_ovf[OVF_MAX * 4];            // rel, dst, src, w-bits

// ---------------- small PTX helpers ---------------------------------------------------
__device__ __forceinline__ u64 pack2(float x) {
    u64 r; asm("mov.b64 %0, {%1, %1};" : "=l"(r) : "f"(x)); return r;
}
__device__ __forceinline__ void ffma2(u64& d, u64 a, u64 b) {
    asm("fma.rn.f32x2 %0, %1, %2, %0;" : "+l"(d) : "l"(a), "l"(b));
}
__device__ __forceinline__ float2 unpack2(u64 v) {
    float2 f; asm("mov.b64 {%0, %1}, %2;" : "=f"(f.x), "=f"(f.y) : "l"(v)); return f;
}
__device__ __forceinline__ __half2 tanh2(__half2 x) {
    u32 xi = *(u32*)&x, yi;
    asm("tanh.approx.f16x2 %0, %1;" : "=r"(yi) : "r"(xi));
    return *(__half2*)&yi;
}
__device__ __forceinline__ u32 smem_u32(const void* p) {
    u32 a; asm("{ .reg .u64 t; cvta.to.shared.u64 t, %1; cvt.u32.u64 %0, t; }" : "=r"(a) : "l"(p));
    return a;
}
__device__ __forceinline__ void ldsm_x4(u32& r0, u32& r1, u32& r2, u32& r3, u32 addr) {
    asm volatile("ldmatrix.sync.aligned.m8n8.x4.shared.b16 {%0,%1,%2,%3}, [%4];"
                 : "=r"(r0), "=r"(r1), "=r"(r2), "=r"(r3) : "r"(addr));
}
// f16 HMMA with f32 accumulate (same shape/layout as bf16 variant)
__device__ __forceinline__ void mma_16816(float* c, u32 a0, u32 a1, u32 a2, u32 a3,
                                          u32 b0, u32 b1) {
    asm volatile(
        "mma.sync.aligned.m16n8k16.row.col.f32.f16.f16.f32 "
        "{%0,%1,%2,%3}, {%4,%5,%6,%7}, {%8,%9}, {%0,%1,%2,%3};"
        : "+f"(c[0]), "+f"(c[1]), "+f"(c[2]), "+f"(c[3])
        : "r"(a0), "r"(a1), "r"(a2), "r"(a3), "r"(b0), "r"(b1));
}
__device__ __forceinline__ u64 pack_h16x4(float x, float y, float z, float w) {
    __half2 p0 = __floats2half2_rn(x, y);
    __half2 p1 = __floats2half2_rn(z, w);
    return (u64)(*(u32*)&p0) | ((u64)(*(u32*)&p1) << 32);
}
__device__ __forceinline__ float4 unpack_h16x4(u64 v) {
    u32 lo = (u32)v, hi = (u32)(v >> 32);
    float2 f0 = __half22float2(*(__half2*)&lo);
    float2 f1 = __half22float2(*(__half2*)&hi);
    return make_float4(f0.x, f0.y, f1.x, f1.y);
}

// ---------------- stage [128x128] f32 weights into paired-f32x2 smem layout -----------
__device__ __forceinline__ void stage_w128(float* Ws, const float* __restrict__ Wsrc,
                                           int tid, int nthreads) {
    for (int idx = tid; idx < DD * DD; idx += nthreads) {
        int j = idx >> 7, k = idx & 127;
        int l, c;
        if (j < 64) { l = j >> 1; c = j & 1; }
        else        { l = (j - 64) >> 1; c = 2 + ((j - 64) & 1); }
        Ws[(k * 32 + l) * 4 + c] = Wsrc[idx];
    }
}

// ---------------- kernel: prep = zero counters + Wcomb = W1 @ W_tran -------------------
__global__ __launch_bounds__(256) void prep_kernel(const float* __restrict__ W1,
                                                   const float* __restrict__ Wt) {
    int i = blockIdx.x * 256 + threadIdx.x;
    if (i < 512 * DD) {
        int h = i >> 7, j = i & 127;
        float acc = 0.f;
#pragma unroll 8
        for (int k = 0; k < DD; k++)
            acc += W1[h * DD + k] * Wt[k * DD + j];
        g_wcomb[i] = acc;
    }
    int stride = gridDim.x * 256;
    for (int k = i; k < 3 * NN; k += stride) g_deg[k] = 0u;
    if (i < 3) g_wsum[i] = 0.f;
    if (i == 3) g_ovf_cnt = 0u;
}

// ---------------- kernel: fill destination buckets (4 edges, batched atomics) ----------
__global__ __launch_bounds__(256) void fill_kernel(
    const int* __restrict__ gs, const int* __restrict__ gd,
    const int* __restrict__ cs, const int* __restrict__ cd,
    const int* __restrict__ ts, const int* __restrict__ td,
    const float* __restrict__ tw) {
    int i = blockIdx.x * blockDim.x + threadIdx.x;   // i < 3*NE/4 = 450000
    if (i >= 3 * NE / 4) return;
    int rel = i / (NE / 4);
    int e4 = i - rel * (NE / 4);

    int4 sv, dv; float4 wv = make_float4(1.f, 1.f, 1.f, 1.f);
    if (rel == 0)      { sv = ((const int4*)gs)[e4]; dv = ((const int4*)gd)[e4]; }
    else if (rel == 1) { sv = ((const int4*)cs)[e4]; dv = ((const int4*)cd)[e4]; }
    else               { sv = ((const int4*)ts)[e4]; dv = ((const int4*)td)[e4];
                         wv = ((const float4*)tw)[e4]; }

    int src[4] = {sv.x, sv.y, sv.z, sv.w};
    int dst[4] = {dv.x, dv.y, dv.z, dv.w};
    float w[4] = {wv.x, wv.y, wv.z, wv.w};

    u32 pos[4];
#pragma unroll
    for (int j = 0; j < 4; j++)
        pos[j] = atomicAdd(&g_deg[rel * NN + dst[j]], 1u);

#pragma unroll
    for (int j = 0; j < 4; j++) {
        if (pos[j] < CAP) {
            g_bucket[(rel * NN + dst[j]) * CAP + pos[j]] = src[j];
            if (rel == 2) g_bw[dst[j] * CAP + pos[j]] = w[j];
        } else {
            u32 o = atomicAdd(&g_ovf_cnt, 1u);
            if (o < OVF_MAX) {
                g_ovf[o * 4 + 0] = rel;
                g_ovf[o * 4 + 1] = dst[j];
                g_ovf[o * 4 + 2] = src[j];
                g_ovf[o * 4 + 3] = __float_as_int(w[j]);
            }
        }
    }
}

// ---------------- kernel: per-destination gather-sum (+inline overflow handling) -------
// Output: f16 aggregates only (att and fuse both consume f16).
__global__ __launch_bounds__(256) void gather_kernel(const float* __restrict__ feat) {
    int warps_total = gridDim.x * (blockDim.x >> 5);
    int gw0 = blockIdx.x * (blockDim.x >> 5) + (threadIdx.x >> 5);
    int lane = threadIdx.x & 31;
    const float4* f4 = (const float4*)feat;

    for (int gw = gw0; gw < 3 * NN; gw += warps_total) {
        int rel = gw / NN, dst = gw - rel * NN;

        u32 d = g_deg[rel * NN + dst];
        u32 lim = d < CAP ? d : CAP;
        const int4* bkv = (const int4*)&g_bucket[(size_t)(rel * NN + dst) * CAP];

        float4 acc = make_float4(0.f, 0.f, 0.f, 0.f);

        if (rel != 2) {
            for (u32 e = 0; e < lim; e += 8) {
                int4 ia = bkv[e >> 2];
                int4 ib = bkv[(e >> 2) + 1];
                int si[8] = {ia.x, ia.y, ia.z, ia.w, ib.x, ib.y, ib.z, ib.w};
                float4 v[8];
#pragma unroll
                for (int j = 0; j < 8; j++)
                    v[j] = (e + j < lim) ? f4[(u32)si[j] * 32u + lane]
                                         : make_float4(0.f, 0.f, 0.f, 0.f);
#pragma unroll
                for (int j = 0; j < 8; j++) {
                    acc.x += v[j].x; acc.y += v[j].y; acc.z += v[j].z; acc.w += v[j].w;
                }
            }
        } else {
            const float4* bwv = (const float4*)&g_bw[(size_t)dst * CAP];
            for (u32 e = 0; e < lim; e += 8) {
                int4 ia = bkv[e >> 2];
                int4 ib = bkv[(e >> 2) + 1];
                float4 wa = bwv[e >> 2];
                float4 wb = bwv[(e >> 2) + 1];
                int si[8] = {ia.x, ia.y, ia.z, ia.w, ib.x, ib.y, ib.z, ib.w};
                float wi[8] = {wa.x, wa.y, wa.z, wa.w, wb.x, wb.y, wb.z, wb.w};
                float4 v[8];
#pragma unroll
                for (int j = 0; j < 8; j++) {
                    bool p = e + j < lim;
                    v[j] = p ? f4[(u32)si[j] * 32u + lane]
                             : make_float4(0.f, 0.f, 0.f, 0.f);
                    if (!p) wi[j] = 0.f;
                }
#pragma unroll
                for (int j = 0; j < 8; j++) {
                    acc.x += v[j].x * wi[j];
                    acc.y += v[j].y * wi[j];
                    acc.z += v[j].z * wi[j];
                    acc.w += v[j].w * wi[j];
                }
            }
        }

        // Inline overflow handling (statistically never taken: P(deg>64) ~ 1e-44)
        if (d > CAP) {
            u32 cnt = g_ovf_cnt;
            if (cnt > OVF_MAX) cnt = OVF_MAX;
            for (u32 o = 0; o < cnt; o++) {
                if (g_ovf[o * 4 + 0] == rel && g_ovf[o * 4 + 1] == dst) {
                    int src = g_ovf[o * 4 + 2];
                    float w = __int_as_float(g_ovf[o * 4 + 3]);
                    float4 v = f4[(u32)src * 32u + lane];
                    acc.x += v.x * w; acc.y += v.y * w;
                    acc.z += v.z * w; acc.w += v.w * w;
                }
            }
        }

        float sc = (rel == 2) ? 1.f : 1.f / fmaxf((float)d, 1.f);
        acc.x *= sc; acc.y *= sc; acc.z *= sc; acc.w *= sc;

        ((u64*)g_aggh)[(u32)gw * 32u + lane] = pack_h16x4(acc.x, acc.y, acc.z, acc.w);
    }
}

// ---------------- kernel: attention HMMA (f16), 512 threads, R10 tile -----------------
#define ATT_LDA 136
#define A_BYTES 34816
#define SM_A0  0
#define SM_B   69632
#define SM_B1  208896
#define SM_W2  210944
#define SMEM_ATT 212992
#define ATT_THREADS 512

__global__ __launch_bounds__(ATT_THREADS) void att_mma_kernel(const float* __restrict__ B1,
                                                              const float* __restrict__ W2) {
    extern __shared__ char smem[];
    u32 sb = smem_u32(smem);
    int tid = threadIdx.x, wid = tid >> 5, lane = tid & 31;

    // Stage B = Wcomb (f32 -> f16), b1, w2
    for (int i = tid; i < 512 * 32; i += ATT_THREADS) {
        int j = i >> 5, q = i & 31;
        float4 v = ((const float4*)g_wcomb)[i];
        *(u64*)(smem + SM_B + (j * ATT_LDA + q * 4) * 2) = pack_h16x4(v.x, v.y, v.z, v.w);
    }
    if (tid < 512) {
        ((float*)(smem + SM_B1))[tid] = B1[tid];
        ((float*)(smem + SM_W2))[tid] = W2[tid];
    }

    // async A-tile stager: 128 rows x 256B via 16B cp.async chunks (2048 chunks)
    auto stage = [&](int t, int bf) {
        if (t < TILES_TOTAL) {
            int rel = t / NTILES;
            int base = (t - rel * NTILES) * 128;
            const char* srcb = (const char*)g_aggh + (size_t)rel * NN * 256;
#pragma unroll
            for (int k2 = 0; k2 < 4; k2++) {
                int i = tid + k2 * ATT_THREADS;
                int row = i >> 4, q = i & 15;
                int node = base + row;
                bool vld = node < NN;
                const char* src = srcb + (size_t)(vld ? node : 0) * 256 + q * 16;
                u32 dsta = sb + SM_A0 + bf * A_BYTES + row * 272 + q * 16;
                int ss = vld ? 16 : 0;
                asm volatile("cp.async.cg.shared.global [%0], [%1], 16, %2;"
                             :: "r"(dsta), "l"(src), "r"(ss) : "memory");
            }
        }
        asm volatile("cp.async.commit_group;" ::: "memory");
    };

    stage(blockIdx.x, 0);
    __syncthreads();

    const float* b1s = (const float*)(smem + SM_B1);
    const float* w2s = (const float*)(smem + SM_W2);

    // Tile-invariant half2 bias/weight pairs; this warp's 32 cols = 4 n-groups of 8
    __half2 bh[4], wh[4];
#pragma unroll
    for (int nn = 0; nn < 4; nn++) {
        int j0 = (wid << 5) + nn * 8 + ((lane & 3) << 1);
        bh[nn] = __floats2half2_rn(b1s[j0], b1s[j0 + 1]);
        wh[nn] = __floats2half2_rn(w2s[j0], w2s[j0 + 1]);
    }

    float racc[3] = {0.f, 0.f, 0.f};
    int buf = 0;
    u32 grp = lane >> 3, l3 = lane & 7;

    for (int t = blockIdx.x; t < TILES_TOTAL; t += gridDim.x) {
        asm volatile("cp.async.wait_group 0;" ::: "memory");
        __syncthreads();
        stage(t + gridDim.x, buf ^ 1);   // overlap next tile load with compute

        int rel = t / NTILES;
        int base = (t - rel * NTILES) * 128;
        u32 abase = sb + SM_A0 + buf * A_BYTES;
        bool full = (base + 128 <= NN);

        float ps = 0.f;
#pragma unroll
        for (int mp = 0; mp < 4; mp++) {
            int m0 = mp * 32;
            float acc[2][4][4];
#pragma unroll
            for (int s = 0; s < 2; s++)
#pragma unroll
                for (int n = 0; n < 4; n++)
#pragma unroll
                    for (int ee = 0; ee < 4; ee++) acc[s][n][ee] = 0.f;

#pragma unroll
            for (int kk = 0; kk < 8; kk++) {
                u32 a0[4], a1[4];
                u32 arow0 = m0 + (lane & 15);
                u32 acol = kk * 16 + ((lane >> 4) << 3);
                ldsm_x4(a0[0], a0[1], a0[2], a0[3], abase + (arow0 * ATT_LDA + acol) * 2);
                ldsm_x4(a1[0], a1[1], a1[2], a1[3],
                        abase + ((arow0 + 16) * ATT_LDA + acol) * 2);

#pragma unroll
                for (int np = 0; np < 2; np++) {
                    u32 b0, b1r, b2, b3;
                    u32 brow = (wid << 5) + np * 16 + ((grp >> 1) << 3) + l3;
                    u32 bcol = kk * 16 + ((grp & 1) << 3);
                    ldsm_x4(b0, b1r, b2, b3, sb + SM_B + (brow * ATT_LDA + bcol) * 2);
                    mma_16816(acc[0][np * 2], a0[0], a0[1], a0[2], a0[3], b0, b1r);
                    mma_16816(acc[1][np * 2], a1[0], a1[1], a1[2], a1[3], b0, b1r);
                    mma_16816(acc[0][np * 2 + 1], a0[0], a0[1], a0[2], a0[3], b2, b3);
                    mma_16816(acc[1][np * 2 + 1], a1[0], a1[1], a1[2], a1[3], b2, b3);
                }
            }

            // Epilogue (f16x2): hsum += wh * tanh(acc + bh)
            __half2 hsum = __floats2half2_rn(0.f, 0.f);
            if (full) {
#pragma unroll
                for (int nn = 0; nn < 4; nn++) {
#pragma unroll
                    for (int s = 0; s < 2; s++) {
                        const float* c = acc[s][nn];
                        __half2 x0 = __hadd2(__floats2half2_rn(c[0], c[1]), bh[nn]);
                        hsum = __hfma2(tanh2(x0), wh[nn], hsum);
                        __half2 x1 = __hadd2(__floats2half2_rn(c[2], c[3]), bh[nn]);
                        hsum = __hfma2(tanh2(x1), wh[nn], hsum);
                    }
                }
            } else {
                bool v0 = (base + m0 + (lane >> 2)) < NN;
                bool v1 = (base + m0 + 8 + (lane >> 2)) < NN;
                bool v2 = (base + m0 + 16 + (lane >> 2)) < NN;
                bool v3 = (base + m0 + 24 + (lane >> 2)) < NN;
#pragma unroll
                for (int nn = 0; nn < 4; nn++) {
#pragma unroll
                    for (int s = 0; s < 2; s++) {
                        const float* c = acc[s][nn];
                        bool pa = s ? v2 : v0;
                        bool pb = s ? v3 : v1;
                        if (pa) {
                            __half2 x = __hadd2(__floats2half2_rn(c[0], c[1]), bh[nn]);
                            hsum = __hfma2(tanh2(x), wh[nn], hsum);
                        }
                        if (pb) {
                            __half2 x = __hadd2(__floats2half2_rn(c[2], c[3]), bh[nn]);
                            hsum = __hfma2(tanh2(x), wh[nn], hsum);
                        }
                    }
                }
            }
            float2 hs = __half22float2(hsum);
            ps += hs.x + hs.y;
        }
        racc[rel] += ps;
        buf ^= 1;
    }

#pragma unroll
    for (int o = 16; o; o >>= 1) {
        racc[0] += __shfl_xor_sync(0xffffffffu, racc[0], o);
        racc[1] += __shfl_xor_sync(0xffffffffu, racc[1], o);
        racc[2] += __shfl_xor_sync(0xffffffffu, racc[2], o);
    }
    if (lane == 0) {
        atomicAdd(&g_wsum[0], racc[0]);
        atomicAdd(&g_wsum[1], racc[1]);
        atomicAdd(&g_wsum[2], racc[2]);
    }
}

// ---------------- kernel: fuse = leaky((b0*geo + b1*trans + b2*cat) @ Wt^T) ------------
// R10 structure (4 nodes/warp, 96KB smem -> 2 CTAs/SM); inputs are f16 aggregates.
__global__ __launch_bounds__(256) void fuse_kernel(const float* __restrict__ Wt,
                                                   float* __restrict__ out) {
    extern __shared__ char smem[];
    float* Ws = (float*)smem;                  // 65536 B
    u64* Zs = (u64*)(smem + 65536);            // 32768 B
    int tid = threadIdx.x;
    stage_w128(Ws, Wt, tid, 256);
    __syncthreads();

    float w0 = g_wsum[0] * (1.f / NN);
    float w1 = g_wsum[1] * (1.f / NN);
    float w2 = g_wsum[2] * (1.f / NN);
    float m = fmaxf(w0, fmaxf(w1, w2));
    float e0 = expf(w0 - m), e1 = expf(w1 - m), e2 = expf(w2 - m);
    float inv = 1.f / (e0 + e1 + e2);
    float b0 = e0 * inv, b1 = e1 * inv, b2 = e2 * inv;

    const ulonglong2* Wv = (const ulonglong2*)Ws;
    int warp = tid >> 5, lane = tid & 31;
    u64* Zw = Zs + warp * 4 * DD;
    const u64* geoh = (const u64*)g_aggh;
    const u64* trnh = geoh + (size_t)NN * 32;
    const u64* cath = trnh + (size_t)NN * 32;

    for (int base = blockIdx.x * 32 + warp * 4; base < NN; base += gridDim.x * 32) {
#pragma unroll
        for (int mm = 0; mm < 4; mm++) {
            int n = base + mm;
            float4 v = make_float4(0.f, 0.f, 0.f, 0.f);
            if (n < NN) {
                float4 g = unpack_h16x4(geoh[(size_t)n * 32 + lane]);
                float4 t = unpack_h16x4(trnh[(size_t)n * 32 + lane]);
                float4 c = unpack_h16x4(cath[(size_t)n * 32 + lane]);
                v.x = b0 * g.x + b1 * t.x + b2 * c.x;
                v.y = b0 * g.y + b1 * t.y + b2 * c.y;
                v.z = b0 * g.z + b1 * t.z + b2 * c.z;
                v.w = b0 * g.w + b1 * t.w + b2 * c.w;
            }
            u64* zp = Zw + mm * DD + lane * 4;
            zp[0] = pack2(v.x); zp[1] = pack2(v.y); zp[2] = pack2(v.z); zp[3] = pack2(v.w);
        }
        __syncwarp();

        u64 acc[4][2];
#pragma unroll
        for (int mm = 0; mm < 4; mm++) { acc[mm][0] = 0ull; acc[mm][1] = 0ull; }

#pragma unroll 4
        for (int k = 0; k < DD; k++) {
            ulonglong2 wv = Wv[k * 32 + lane];
#pragma unroll
            for (int mm = 0; mm < 4; mm++) {
                u64 zz = Zw[mm * DD + k];
                ffma2(acc[mm][0], zz, wv.x);
                ffma2(acc[mm][1], zz, wv.y);
            }
        }

#pragma unroll
        for (int mm = 0; mm < 4; mm++) {
            int n = base + mm;
            if (n < NN) {
                float2 p0 = unpack2(acc[mm][0]);
                float2 p1 = unpack2(acc[mm][1]);
                p0.x = (p0.x >= 0.f) ? p0.x : 0.2f * p0.x;
                p0.y = (p0.y >= 0.f) ? p0.y : 0.2f * p0.y;
                p1.x = (p1.x >= 0.f) ? p1.x : 0.2f * p1.x;
                p1.y = (p1.y >= 0.f) ? p1.y : 0.2f * p1.y;
                ((float2*)out)[n * 64 + lane] = p0;
                ((float2*)out)[n * 64 + 32 + lane] = p1;
            }
        }
        __syncwarp();
    }
}

// ---------------- launcher -------------------------------------------------------------
extern "C" void kernel_launch(void* const* d_in, const int* in_sizes, int n_in,
                              void* d_out, int out_size) {
    const float* feat = (const float*)d_in[0];
    const float* Wt   = (const float*)d_in[1];
    const float* w1   = (const float*)d_in[2];
    const float* b1   = (const float*)d_in[3];
    const float* w2   = (const float*)d_in[4];
    const float* tw   = (const float*)d_in[5];
    const int* gs = (const int*)d_in[6];
    const int* gd = (const int*)d_in[7];
    const int* cs = (const int*)d_in[8];
    const int* cd = (const int*)d_in[9];
    const int* ts = (const int*)d_in[10];
    const int* td = (const int*)d_in[11];
    float* out = (float*)d_out;

    const int SMEM_FUSE = 65536 + 32768;
    cudaFuncSetAttribute(att_mma_kernel, cudaFuncAttributeMaxDynamicSharedMemorySize, SMEM_ATT);
    cudaFuncSetAttribute(fuse_kernel, cudaFuncAttributeMaxDynamicSharedMemorySize, SMEM_FUSE);

    prep_kernel<<<512, 256>>>(w1, Wt);
    fill_kernel<<<(3 * NE / 4 + 255) / 256, 256>>>(gs, gd, cs, cd, ts, td, tw);
    gather_kernel<<<2048, 256>>>(feat);
    att_mma_kernel<<<148, ATT_THREADS, SMEM_ATT>>>(b1, w2);
    fuse_kernel<<<296, 256, SMEM_FUSE>>>(Wt, out);
}

// round 16
// speedup vs baseline: 1.4771x; 1.2801x over previous
#include <cuda_runtime.h>
#include <cuda_fp16.h>
#include <cstdint>
#include <math.h>

#define NN 100000
#define NE 600000
#define DD 128
#define CAP 64
#define NTILES 782                 // ceil(100000/128)
#define TILES_TOTAL (3 * NTILES)
#define OVF_MAX 4096

typedef unsigned long long u64;
typedef unsigned int u32;

// ---------------- device scratch ------------------------------------------------------
__device__ __half g_aggh[3 * NN * DD];        // f16 aggregates: [geo, trans, cat]
__device__ u32 g_deg[3 * NN];
__device__ int g_bucket[3 * NN * CAP];
__device__ float g_bw[NN * CAP];              // weights for trans buckets
__device__ float g_wcomb[512 * DD];           // W1 @ W_tran
__device__ float g_wsum[3];
__device__ u32 g_ovf_cnt;
__device__ int g_ovf[OVF_MAX * 4];            // rel, dst, src, w-bits

// ---------------- small PTX helpers ---------------------------------------------------
__device__ __forceinline__ __half2 tanh2(__half2 x) {
    u32 xi = *(u32*)&x, yi;
    asm("tanh.approx.f16x2 %0, %1;" : "=r"(yi) : "r"(xi));
    return *(__half2*)&yi;
}
__device__ __forceinline__ u32 smem_u32(const void* p) {
    u32 a; asm("{ .reg .u64 t; cvta.to.shared.u64 t, %1; cvt.u32.u64 %0, t; }" : "=r"(a) : "l"(p));
    return a;
}
__device__ __forceinline__ void ldsm_x4(u32& r0, u32& r1, u32& r2, u32& r3, u32 addr) {
    asm volatile("ldmatrix.sync.aligned.m8n8.x4.shared.b16 {%0,%1,%2,%3}, [%4];"
                 : "=r"(r0), "=r"(r1), "=r"(r2), "=r"(r3) : "r"(addr));
}
// f16 HMMA with f32 accumulate
__device__ __forceinline__ void mma_16816(float* c, u32 a0, u32 a1, u32 a2, u32 a3,
                                          u32 b0, u32 b1) {
    asm volatile(
        "mma.sync.aligned.m16n8k16.row.col.f32.f16.f16.f32 "
        "{%0,%1,%2,%3}, {%4,%5,%6,%7}, {%8,%9}, {%0,%1,%2,%3};"
        : "+f"(c[0]), "+f"(c[1]), "+f"(c[2]), "+f"(c[3])
        : "r"(a0), "r"(a1), "r"(a2), "r"(a3), "r"(b0), "r"(b1));
}
__device__ __forceinline__ u64 pack_h16x4(float x, float y, float z, float w) {
    __half2 p0 = __floats2half2_rn(x, y);
    __half2 p1 = __floats2half2_rn(z, w);
    return (u64)(*(u32*)&p0) | ((u64)(*(u32*)&p1) << 32);
}
__device__ __forceinline__ float4 unpack_h16x4(u64 v) {
    u32 lo = (u32)v, hi = (u32)(v >> 32);
    float2 f0 = __half22float2(*(__half2*)&lo);
    float2 f1 = __half22float2(*(__half2*)&hi);
    return make_float4(f0.x, f0.y, f1.x, f1.y);
}
__device__ __forceinline__ float leaky(float x) { return (x >= 0.f) ? x : 0.2f * x; }

// ---------------- kernel: prep = zero counters + Wcomb = W1 @ W_tran -------------------
__global__ __launch_bounds__(256) void prep_kernel(const float* __restrict__ W1,
                                                   const float* __restrict__ Wt) {
    int i = blockIdx.x * 256 + threadIdx.x;
    if (i < 512 * DD) {
        int h = i >> 7, j = i & 127;
        float acc = 0.f;
#pragma unroll 8
        for (int k = 0; k < DD; k++)
            acc += W1[h * DD + k] * Wt[k * DD + j];
        g_wcomb[i] = acc;
    }
    int stride = gridDim.x * 256;
    for (int k = i; k < 3 * NN; k += stride) g_deg[k] = 0u;
    if (i < 3) g_wsum[i] = 0.f;
    if (i == 3) g_ovf_cnt = 0u;
}

// ---------------- kernel: fill destination buckets (4 edges, batched atomics) ----------
__global__ __launch_bounds__(256) void fill_kernel(
    const int* __restrict__ gs, const int* __restrict__ gd,
    const int* __restrict__ cs, const int* __restrict__ cd,
    const int* __restrict__ ts, const int* __restrict__ td,
    const float* __restrict__ tw) {
    int i = blockIdx.x * blockDim.x + threadIdx.x;   // i < 3*NE/4 = 450000
    if (i >= 3 * NE / 4) return;
    int rel = i / (NE / 4);
    int e4 = i - rel * (NE / 4);

    int4 sv, dv; float4 wv = make_float4(1.f, 1.f, 1.f, 1.f);
    if (rel == 0)      { sv = ((const int4*)gs)[e4]; dv = ((const int4*)gd)[e4]; }
    else if (rel == 1) { sv = ((const int4*)cs)[e4]; dv = ((const int4*)cd)[e4]; }
    else               { sv = ((const int4*)ts)[e4]; dv = ((const int4*)td)[e4];
                         wv = ((const float4*)tw)[e4]; }

    int src[4] = {sv.x, sv.y, sv.z, sv.w};
    int dst[4] = {dv.x, dv.y, dv.z, dv.w};
    float w[4] = {wv.x, wv.y, wv.z, wv.w};

    u32 pos[4];
#pragma unroll
    for (int j = 0; j < 4; j++)
        pos[j] = atomicAdd(&g_deg[rel * NN + dst[j]], 1u);

#pragma unroll
    for (int j = 0; j < 4; j++) {
        if (pos[j] < CAP) {
            g_bucket[(rel * NN + dst[j]) * CAP + pos[j]] = src[j];
            if (rel == 2) g_bw[dst[j] * CAP + pos[j]] = w[j];
        } else {
            u32 o = atomicAdd(&g_ovf_cnt, 1u);
            if (o < OVF_MAX) {
                g_ovf[o * 4 + 0] = rel;
                g_ovf[o * 4 + 1] = dst[j];
                g_ovf[o * 4 + 2] = src[j];
                g_ovf[o * 4 + 3] = __float_as_int(w[j]);
            }
        }
    }
}

// ---------------- kernel: per-destination gather-sum (+inline overflow handling) -------
__global__ __launch_bounds__(256) void gather_kernel(const float* __restrict__ feat) {
    int warps_total = gridDim.x * (blockDim.x >> 5);
    int gw0 = blockIdx.x * (blockDim.x >> 5) + (threadIdx.x >> 5);
    int lane = threadIdx.x & 31;
    const float4* f4 = (const float4*)feat;

    for (int gw = gw0; gw < 3 * NN; gw += warps_total) {
        int rel = gw / NN, dst = gw - rel * NN;

        u32 d = g_deg[rel * NN + dst];
        u32 lim = d < CAP ? d : CAP;
        const int4* bkv = (const int4*)&g_bucket[(size_t)(rel * NN + dst) * CAP];

        float4 acc = make_float4(0.f, 0.f, 0.f, 0.f);

        if (rel != 2) {
            for (u32 e = 0; e < lim; e += 8) {
                int4 ia = bkv[e >> 2];
                int4 ib = bkv[(e >> 2) + 1];
                int si[8] = {ia.x, ia.y, ia.z, ia.w, ib.x, ib.y, ib.z, ib.w};
                float4 v[8];
#pragma unroll
                for (int j = 0; j < 8; j++)
                    v[j] = (e + j < lim) ? f4[(u32)si[j] * 32u + lane]
                                         : make_float4(0.f, 0.f, 0.f, 0.f);
#pragma unroll
                for (int j = 0; j < 8; j++) {
                    acc.x += v[j].x; acc.y += v[j].y; acc.z += v[j].z; acc.w += v[j].w;
                }
            }
        } else {
            const float4* bwv = (const float4*)&g_bw[(size_t)dst * CAP];
            for (u32 e = 0; e < lim; e += 8) {
                int4 ia = bkv[e >> 2];
                int4 ib = bkv[(e >> 2) + 1];
                float4 wa = bwv[e >> 2];
                float4 wb = bwv[(e >> 2) + 1];
                int si[8] = {ia.x, ia.y, ia.z, ia.w, ib.x, ib.y, ib.z, ib.w};
                float wi[8] = {wa.x, wa.y, wa.z, wa.w, wb.x, wb.y, wb.z, wb.w};
                float4 v[8];
#pragma unroll
                for (int j = 0; j < 8; j++) {
                    bool p = e + j < lim;
                    v[j] = p ? f4[(u32)si[j] * 32u + lane]
                             : make_float4(0.f, 0.f, 0.f, 0.f);
                    if (!p) wi[j] = 0.f;
                }
#pragma unroll
                for (int j = 0; j < 8; j++) {
                    acc.x += v[j].x * wi[j];
                    acc.y += v[j].y * wi[j];
                    acc.z += v[j].z * wi[j];
                    acc.w += v[j].w * wi[j];
                }
            }
        }

        if (d > CAP) {
            u32 cnt = g_ovf_cnt;
            if (cnt > OVF_MAX) cnt = OVF_MAX;
            for (u32 o = 0; o < cnt; o++) {
                if (g_ovf[o * 4 + 0] == rel && g_ovf[o * 4 + 1] == dst) {
                    int src = g_ovf[o * 4 + 2];
                    float w = __int_as_float(g_ovf[o * 4 + 3]);
                    float4 v = f4[(u32)src * 32u + lane];
                    acc.x += v.x * w; acc.y += v.y * w;
                    acc.z += v.z * w; acc.w += v.w * w;
                }
            }
        }

        float sc = (rel == 2) ? 1.f : 1.f / fmaxf((float)d, 1.f);
        acc.x *= sc; acc.y *= sc; acc.z *= sc; acc.w *= sc;

        ((u64*)g_aggh)[(u32)gw * 32u + lane] = pack_h16x4(acc.x, acc.y, acc.z, acc.w);
    }
}

// ---------------- kernel: attention HMMA (f16), 512 threads, R10 tile -----------------
#define ATT_LDA 136
#define A_BYTES 34816
#define SM_A0  0
#define SM_B   69632
#define SM_B1  208896
#define SM_W2  210944
#define SMEM_ATT 212992
#define ATT_THREADS 512

__global__ __launch_bounds__(ATT_THREADS) void att_mma_kernel(const float* __restrict__ B1,
                                                              const float* __restrict__ W2) {
    extern __shared__ char smem[];
    u32 sb = smem_u32(smem);
    int tid = threadIdx.x, wid = tid >> 5, lane = tid & 31;

    // Stage B = Wcomb (f32 -> f16), b1, w2
    for (int i = tid; i < 512 * 32; i += ATT_THREADS) {
        int j = i >> 5, q = i & 31;
        float4 v = ((const float4*)g_wcomb)[i];
        *(u64*)(smem + SM_B + (j * ATT_LDA + q * 4) * 2) = pack_h16x4(v.x, v.y, v.z, v.w);
    }
    if (tid < 512) {
        ((float*)(smem + SM_B1))[tid] = B1[tid];
        ((float*)(smem + SM_W2))[tid] = W2[tid];
    }

    auto stage = [&](int t, int bf) {
        if (t < TILES_TOTAL) {
            int rel = t / NTILES;
            int base = (t - rel * NTILES) * 128;
            const char* srcb = (const char*)g_aggh + (size_t)rel * NN * 256;
#pragma unroll
            for (int k2 = 0; k2 < 4; k2++) {
                int i = tid + k2 * ATT_THREADS;
                int row = i >> 4, q = i & 15;
                int node = base + row;
                bool vld = node < NN;
                const char* src = srcb + (size_t)(vld ? node : 0) * 256 + q * 16;
                u32 dsta = sb + SM_A0 + bf * A_BYTES + row * 272 + q * 16;
                int ss = vld ? 16 : 0;
                asm volatile("cp.async.cg.shared.global [%0], [%1], 16, %2;"
                             :: "r"(dsta), "l"(src), "r"(ss) : "memory");
            }
        }
        asm volatile("cp.async.commit_group;" ::: "memory");
    };

    stage(blockIdx.x, 0);
    __syncthreads();

    const float* b1s = (const float*)(smem + SM_B1);
    const float* w2s = (const float*)(smem + SM_W2);

    __half2 bh[4], wh[4];
#pragma unroll
    for (int nn = 0; nn < 4; nn++) {
        int j0 = (wid << 5) + nn * 8 + ((lane & 3) << 1);
        bh[nn] = __floats2half2_rn(b1s[j0], b1s[j0 + 1]);
        wh[nn] = __floats2half2_rn(w2s[j0], w2s[j0 + 1]);
    }

    float racc[3] = {0.f, 0.f, 0.f};
    int buf = 0;
    u32 grp = lane >> 3, l3 = lane & 7;

    for (int t = blockIdx.x; t < TILES_TOTAL; t += gridDim.x) {
        asm volatile("cp.async.wait_group 0;" ::: "memory");
        __syncthreads();
        stage(t + gridDim.x, buf ^ 1);

        int rel = t / NTILES;
        int base = (t - rel * NTILES) * 128;
        u32 abase = sb + SM_A0 + buf * A_BYTES;
        bool full = (base + 128 <= NN);

        float ps = 0.f;
#pragma unroll
        for (int mp = 0; mp < 4; mp++) {
            int m0 = mp * 32;
            float acc[2][4][4];
#pragma unroll
            for (int s = 0; s < 2; s++)
#pragma unroll
                for (int n = 0; n < 4; n++)
#pragma unroll
                    for (int ee = 0; ee < 4; ee++) acc[s][n][ee] = 0.f;

#pragma unroll
            for (int kk = 0; kk < 8; kk++) {
                u32 a0[4], a1[4];
                u32 arow0 = m0 + (lane & 15);
                u32 acol = kk * 16 + ((lane >> 4) << 3);
                ldsm_x4(a0[0], a0[1], a0[2], a0[3], abase + (arow0 * ATT_LDA + acol) * 2);
                ldsm_x4(a1[0], a1[1], a1[2], a1[3],
                        abase + ((arow0 + 16) * ATT_LDA + acol) * 2);

#pragma unroll
                for (int np = 0; np < 2; np++) {
                    u32 b0, b1r, b2, b3;
                    u32 brow = (wid << 5) + np * 16 + ((grp >> 1) << 3) + l3;
                    u32 bcol = kk * 16 + ((grp & 1) << 3);
                    ldsm_x4(b0, b1r, b2, b3, sb + SM_B + (brow * ATT_LDA + bcol) * 2);
                    mma_16816(acc[0][np * 2], a0[0], a0[1], a0[2], a0[3], b0, b1r);
                    mma_16816(acc[1][np * 2], a1[0], a1[1], a1[2], a1[3], b0, b1r);
                    mma_16816(acc[0][np * 2 + 1], a0[0], a0[1], a0[2], a0[3], b2, b3);
                    mma_16816(acc[1][np * 2 + 1], a1[0], a1[1], a1[2], a1[3], b2, b3);
                }
            }

            __half2 hsum = __floats2half2_rn(0.f, 0.f);
            if (full) {
#pragma unroll
                for (int nn = 0; nn < 4; nn++) {
#pragma unroll
                    for (int s = 0; s < 2; s++) {
                        const float* c = acc[s][nn];
                        __half2 x0 = __hadd2(__floats2half2_rn(c[0], c[1]), bh[nn]);
                        hsum = __hfma2(tanh2(x0), wh[nn], hsum);
                        __half2 x1 = __hadd2(__floats2half2_rn(c[2], c[3]), bh[nn]);
                        hsum = __hfma2(tanh2(x1), wh[nn], hsum);
                    }
                }
            } else {
                bool v0 = (base + m0 + (lane >> 2)) < NN;
                bool v1 = (base + m0 + 8 + (lane >> 2)) < NN;
                bool v2 = (base + m0 + 16 + (lane >> 2)) < NN;
                bool v3 = (base + m0 + 24 + (lane >> 2)) < NN;
#pragma unroll
                for (int nn = 0; nn < 4; nn++) {
#pragma unroll
                    for (int s = 0; s < 2; s++) {
                        const float* c = acc[s][nn];
                        bool pa = s ? v2 : v0;
                        bool pb = s ? v3 : v1;
                        if (pa) {
                            __half2 x = __hadd2(__floats2half2_rn(c[0], c[1]), bh[nn]);
                            hsum = __hfma2(tanh2(x), wh[nn], hsum);
                        }
                        if (pb) {
                            __half2 x = __hadd2(__floats2half2_rn(c[2], c[3]), bh[nn]);
                            hsum = __hfma2(tanh2(x), wh[nn], hsum);
                        }
                    }
                }
            }
            float2 hs = __half22float2(hsum);
            ps += hs.x + hs.y;
        }
        racc[rel] += ps;
        buf ^= 1;
    }

#pragma unroll
    for (int o = 16; o; o >>= 1) {
        racc[0] += __shfl_xor_sync(0xffffffffu, racc[0], o);
        racc[1] += __shfl_xor_sync(0xffffffffu, racc[1], o);
        racc[2] += __shfl_xor_sync(0xffffffffu, racc[2], o);
    }
    if (lane == 0) {
        atomicAdd(&g_wsum[0], racc[0]);
        atomicAdd(&g_wsum[1], racc[1]);
        atomicAdd(&g_wsum[2], racc[2]);
    }
}

// ---------------- kernel: fuse via f16 HMMA --------------------------------------------
// out = leaky((b0*geo + b1*trans + b2*cat) @ Wt^T); A = beta-combined f16 z-tile,
// B = Wt f16 [128 x 128]. 256 threads, warp = (mp, nhalf): 32 rows x 64 cols.
// smem: A @0 (34816), B @34816 (34816) = 69632 -> 2+ CTAs/SM.
#define FS_A 0
#define FS_B 34816
#define SMEM_FUSE 69632

__global__ __launch_bounds__(256) void fuse_mma_kernel(const float* __restrict__ Wt,
                                                       float* __restrict__ out) {
    extern __shared__ char smem[];
    u32 sb = smem_u32(smem);
    int tid = threadIdx.x, wid = tid >> 5, lane = tid & 31;
    int mp = wid >> 1, nh = wid & 1;
    u32 grp = lane >> 3, l3 = lane & 7;

    float w0 = g_wsum[0] * (1.f / NN);
    float w1 = g_wsum[1] * (1.f / NN);
    float w2 = g_wsum[2] * (1.f / NN);
    float m = fmaxf(w0, fmaxf(w1, w2));
    float e0 = expf(w0 - m), e1 = expf(w1 - m), e2 = expf(w2 - m);
    float inv = 1.f / (e0 + e1 + e2);
    float b0 = e0 * inv, b1 = e1 * inv, b2 = e2 * inv;

    // Stage B = Wt [j=0..127][k] f32 -> f16 (K-major rows)
    for (int i = tid; i < 128 * 32; i += 256) {
        int j = i >> 5, q = i & 31;
        float4 v = ((const float4*)Wt)[i];
        *(u64*)(smem + FS_B + (j * ATT_LDA + q * 4) * 2) = pack_h16x4(v.x, v.y, v.z, v.w);
    }

    const u64* geoh = (const u64*)g_aggh;
    const u64* trnh = geoh + (size_t)NN * 32;
    const u64* cath = trnh + (size_t)NN * 32;

    for (int t = blockIdx.x; t < NTILES; t += gridDim.x) {
        int base = t * 128;
        __syncthreads();   // protect A buffer from previous iteration's readers

        // Stage A: beta-combined z tile, f32 combine -> f16
        for (int i = tid; i < 128 * 32; i += 256) {
            int row = i >> 5, q = i & 31;
            int node = base + row;
            u64 zv = 0ull;
            if (node < NN) {
                float4 g = unpack_h16x4(geoh[(size_t)node * 32 + q]);
                float4 tt = unpack_h16x4(trnh[(size_t)node * 32 + q]);
                float4 c = unpack_h16x4(cath[(size_t)node * 32 + q]);
                zv = pack_h16x4(b0 * g.x + b1 * tt.x + b2 * c.x,
                                b0 * g.y + b1 * tt.y + b2 * c.y,
                                b0 * g.z + b1 * tt.z + b2 * c.z,
                                b0 * g.w + b1 * tt.w + b2 * c.w);
            }
            *(u64*)(smem + FS_A + (row * ATT_LDA + q * 4) * 2) = zv;
        }
        __syncthreads();

        float acc[2][8][4];
#pragma unroll
        for (int s = 0; s < 2; s++)
#pragma unroll
            for (int n = 0; n < 8; n++)
#pragma unroll
                for (int ee = 0; ee < 4; ee++) acc[s][n][ee] = 0.f;

#pragma unroll
        for (int kk = 0; kk < 8; kk++) {
            u32 a0[4], a1[4];
            u32 arow0 = mp * 32 + (lane & 15);
            u32 acol = kk * 16 + ((lane >> 4) << 3);
            ldsm_x4(a0[0], a0[1], a0[2], a0[3], sb + FS_A + (arow0 * ATT_LDA + acol) * 2);
            ldsm_x4(a1[0], a1[1], a1[2], a1[3],
                    sb + FS_A + ((arow0 + 16) * ATT_LDA + acol) * 2);

#pragma unroll
            for (int np = 0; np < 4; np++) {
                u32 b0r, b1r, b2r, b3r;
                u32 brow = nh * 64 + np * 16 + ((grp >> 1) << 3) + l3;
                u32 bcol = kk * 16 + ((grp & 1) << 3);
                ldsm_x4(b0r, b1r, b2r, b3r, sb + FS_B + (brow * ATT_LDA + bcol) * 2);
                mma_16816(acc[0][np * 2], a0[0], a0[1], a0[2], a0[3], b0r, b1r);
                mma_16816(acc[1][np * 2], a1[0], a1[1], a1[2], a1[3], b0r, b1r);
                mma_16816(acc[0][np * 2 + 1], a0[0], a0[1], a0[2], a0[3], b2r, b3r);
                mma_16816(acc[1][np * 2 + 1], a1[0], a1[1], a1[2], a1[3], b2r, b3r);
            }
        }

        // Epilogue: leaky + store f32
#pragma unroll
        for (int s = 0; s < 2; s++) {
            int r0 = base + mp * 32 + s * 16 + (lane >> 2);
#pragma unroll
            for (int ng = 0; ng < 8; ng++) {
                int col = nh * 64 + ng * 8 + ((lane & 3) << 1);
                const float* c = acc[s][ng];
                if (r0 < NN) {
                    float2 o0 = make_float2(leaky(c[0]), leaky(c[1]));
                    *(float2*)&out[(size_t)r0 * DD + col] = o0;
                }
                if (r0 + 8 < NN) {
                    float2 o1 = make_float2(leaky(c[2]), leaky(c[3]));
                    *(float2*)&out[(size_t)(r0 + 8) * DD + col] = o1;
                }
            }
        }
    }
}

// ---------------- launcher -------------------------------------------------------------
extern "C" void kernel_launch(void* const* d_in, const int* in_sizes, int n_in,
                              void* d_out, int out_size) {
    const float* feat = (const float*)d_in[0];
    const float* Wt   = (const float*)d_in[1];
    const float* w1   = (const float*)d_in[2];
    const float* b1   = (const float*)d_in[3];
    const float* w2   = (const float*)d_in[4];
    const float* tw   = (const float*)d_in[5];
    const int* gs = (const int*)d_in[6];
    const int* gd = (const int*)d_in[7];
    const int* cs = (const int*)d_in[8];
    const int* cd = (const int*)d_in[9];
    const int* ts = (const int*)d_in[10];
    const int* td = (const int*)d_in[11];
    float* out = (float*)d_out;

    cudaFuncSetAttribute(att_mma_kernel, cudaFuncAttributeMaxDynamicSharedMemorySize, SMEM_ATT);
    cudaFuncSetAttribute(fuse_mma_kernel, cudaFuncAttributeMaxDynamicSharedMemorySize, SMEM_FUSE);

    prep_kernel<<<512, 256>>>(w1, Wt);
    fill_kernel<<<(3 * NE / 4 + 255) / 256, 256>>>(gs, gd, cs, cd, ts, td, tw);
    gather_kernel<<<2048, 256>>>(feat);
    att_mma_kernel<<<148, ATT_THREADS, SMEM_ATT>>>(b1, w2);
    fuse_mma_kernel<<<296, 256, SMEM_FUSE>>>(Wt, out);
}